// round 12
// baseline (speedup 1.0000x reference)
#include <cuda_runtime.h>
#include <cuda_fp16.h>

// QuantizedBatchNorm3d: x [8,64,32,64,64] fp32, weight[64], bias[64] -> y same shape.
// fake_quant(exp=5, sig=10, RNE) == IEEE fp16 round-trip for all reachable values.
//
// R12: R11's co-resident fused kernel + barrier-idle prefetch. After publishing
// partials, every thread issues prefetch.global.L2 for the first half of its
// phase-2 region (4 x 128B lines/thread, no live regs), converting per-channel
// barrier spin time into useful DRAM fills. Phase 2 walks FORWARD so the
// prefetched lines are consumed first (short eviction window); the tail of the
// region rides phase-1 L2 residual.

#define NB        8
#define NC        64
#define SPATIAL   (32*64*64)          // 2^17 elements per (n,c) slice
#define CPC       (NB*SPATIAL)        // 2^20 elements per channel
#define FBLOCKS   1024
#define FTHREADS  256
#define BPB_F4    16384               // float4 per block (half of a slice)
#define PARTS     16                  // partial blocks per channel

__device__ float    g_psum[NC * PARTS];
__device__ float    g_psq [NC * PARTS];
__device__ unsigned g_cnt   [NC];     // zero-init; reset via passed-handshake
__device__ unsigned g_passed[NC];

__device__ __forceinline__ float fq1(float v) {
    return __half2float(__float2half_rn(v));
}
__device__ __forceinline__ float2 fq2(float a, float b) {
    __half2 h = __floats2half2_rn(a, b);
    return __half22float2(h);
}

__global__ void __launch_bounds__(FTHREADS, 7)
qbn_fused(const float* __restrict__ x,
          const float* __restrict__ weight,
          const float* __restrict__ bias,
          float* __restrict__ out) {
    __shared__ float  sh_s[FTHREADS / 32], sh_q[FTHREADS / 32];
    __shared__ float4 sh_p;

    const int b = blockIdx.x;
    const int t = threadIdx.x;
    const int c = b >> 4;             // channel: 16 bid-contiguous blocks each
    const int j = b & 15;             // piece within channel
    const int n = j >> 1;             // batch index
    const int h = j & 1;              // half of the (n,c) slice

    const size_t base = (size_t)(n * NC + c) * 32768 + (size_t)h * BPB_F4;
    const float4* xs = reinterpret_cast<const float4*>(x)  + base;
    float4*       ys = reinterpret_cast<float4*>(out)      + base;

    // ---------------- Phase 1: reduce own 16384-float4 region ----------------
    float s = 0.f, sq = 0.f;
    #pragma unroll 1
    for (int g = 0; g < 16; g++) {
        float4 v[4];
        #pragma unroll
        for (int k = 0; k < 4; k++)
            v[k] = xs[(g * 4 + k) * FTHREADS + t];
        #pragma unroll
        for (int k = 0; k < 4; k++) {
            float2 a  = fq2(v[k].x, v[k].y);
            float2 b2 = fq2(v[k].z, v[k].w);
            s  += (a.x + a.y) + (b2.x + b2.y);
            sq += a.x*a.x + a.y*a.y + b2.x*b2.x + b2.y*b2.y;
        }
    }

    const int lane = t & 31, w = t >> 5;
    #pragma unroll
    for (int o = 16; o > 0; o >>= 1) {
        s  += __shfl_down_sync(0xffffffffu, s,  o);
        sq += __shfl_down_sync(0xffffffffu, sq, o);
    }
    if (lane == 0) { sh_s[w] = s; sh_q[w] = sq; }
    __syncthreads();
    if (w == 0) {
        s  = (lane < 8) ? sh_s[lane] : 0.f;
        sq = (lane < 8) ? sh_q[lane] : 0.f;
        #pragma unroll
        for (int o = 4; o > 0; o >>= 1) {
            s  += __shfl_down_sync(0xffffffffu, s,  o);
            sq += __shfl_down_sync(0xffffffffu, sq, o);
        }
        if (lane == 0) {
            g_psum[c * PARTS + j] = s;
            g_psq [c * PARTS + j] = sq;
            unsigned old;
            asm volatile("atom.release.gpu.global.add.u32 %0, [%1], %2;"
                         : "=r"(old) : "l"(&g_cnt[c]), "r"(1u) : "memory");
            (void)old;
        }
    }

    // -------- Barrier-idle prefetch: first half of own phase-2 region --------
    // 16384 float4 = 256KB = 2048 lines; prefetch lines [0,1024): 4 per thread.
    {
        const char* xb = reinterpret_cast<const char*>(xs);
        #pragma unroll
        for (int k = 0; k < 4; k++)
            asm volatile("prefetch.global.L2 [%0];"
                         :: "l"(xb + (size_t)(t + k * FTHREADS) * 128));
    }

    // ------- Per-channel barrier (16 co-resident blocks) + param finalize -------
    if (t < PARTS) {
        unsigned vv;
        for (;;) {
            asm volatile("ld.acquire.gpu.global.u32 %0, [%1];"
                         : "=r"(vv) : "l"(&g_cnt[c]) : "memory");
            if (vv >= (unsigned)PARTS) break;
            __nanosleep(64);
        }
        float ss = g_psum[c * PARTS + t];
        float qq = g_psq [c * PARTS + t];
        #pragma unroll
        for (int o = 8; o > 0; o >>= 1) {
            ss += __shfl_down_sync(0xffffu, ss, o);
            qq += __shfl_down_sync(0xffffu, qq, o);
        }
        if (t == 0) {
            // Reset handshake: 16th block past the barrier reclaims the counters.
            unsigned old = atomicAdd(&g_passed[c], 1u);
            if (old == (unsigned)(PARTS - 1)) { g_cnt[c] = 0u; g_passed[c] = 0u; }

            const float inv_n = 1.0f / (float)CPC;
            float mean = ss * inv_n;
            float var  = qq * inv_n - mean * mean;
            float mean_q  = fq1(mean);
            float var_q   = fq1(var);
            float inv_std = 1.0f / sqrtf(var_q + 1e-5f);
            float w_q     = fq1(weight[c]);
            float b_q     = fq1(bias[c]);
            sh_p = make_float4(mean_q, inv_std, w_q, b_q);
        }
    }
    __syncthreads();
    const float4 p = sh_p;            // {mean, inv_std, w, b}

    // ------- Phase 2: forward walk (prefetched lines first), normalize + quant -------
    #pragma unroll 1
    for (int g = 0; g < 16; g++) {
        float4 v[4];
        #pragma unroll
        for (int k = 0; k < 4; k++)
            v[k] = __ldcs(xs + (g * 4 + k) * FTHREADS + t);
        #pragma unroll
        for (int k = 0; k < 4; k++) {
            float2 a  = fq2(v[k].x, v[k].y);
            float2 b2 = fq2(v[k].z, v[k].w);
            float y0 = fmaf(p.z, (a.x  - p.x) * p.y, p.w);
            float y1 = fmaf(p.z, (a.y  - p.x) * p.y, p.w);
            float y2 = fmaf(p.z, (b2.x - p.x) * p.y, p.w);
            float y3 = fmaf(p.z, (b2.y - p.x) * p.y, p.w);
            float2 q0 = fq2(y0, y1);
            float2 q1 = fq2(y2, y3);
            __stcs(ys + (g * 4 + k) * FTHREADS + t,
                   make_float4(q0.x, q0.y, q1.x, q1.y));
        }
    }
}

extern "C" void kernel_launch(void* const* d_in, const int* in_sizes, int n_in,
                              void* d_out, int out_size) {
    const float* x      = (const float*)d_in[0];
    const float* weight = (const float*)d_in[1];
    const float* bias   = (const float*)d_in[2];
    float* out = (float*)d_out;

    qbn_fused<<<FBLOCKS, FTHREADS>>>(x, weight, bias, out);
}

// round 13
// speedup vs baseline: 1.1102x; 1.1102x over previous
#include <cuda_runtime.h>
#include <cuda_fp16.h>

// QuantizedBatchNorm3d: x [8,64,32,64,64] fp32, weight[64], bias[64] -> y same shape.
// fake_quant(exp=5, sig=10, RNE) == IEEE fp16 round-trip for all reachable values.
//
// R13: fused one-kernel (R11 core) with: (a) 512 blocks x 512 thr, 4/SM ->
// 64 warps/SM and whole grid co-resident; 8 siblings per channel barrier.
// (b) policy-split phase 1: first half __ldcs (evict-first), second half
// default -> the 64MB second-half working set stays L2-resident. (c) phase 2
// walks backward, harvesting that resident half before touching DRAM.

#define NB        8
#define NC        64
#define CPC       (NB*32*64*64)       // 2^20 elements per channel
#define FBLOCKS   512
#define FTHREADS  512
#define SLICE_F4  32768               // float4 per (n,c) slice = per block
#define PARTS     8                   // sibling blocks per channel

__device__ float    g_psum[NC * PARTS];
__device__ float    g_psq [NC * PARTS];
__device__ unsigned g_cnt   [NC];     // zero-init; reset via passed-handshake
__device__ unsigned g_passed[NC];

__device__ __forceinline__ float fq1(float v) {
    return __half2float(__float2half_rn(v));
}
__device__ __forceinline__ float2 fq2(float a, float b) {
    __half2 h = __floats2half2_rn(a, b);
    return __half22float2(h);
}

__global__ void __launch_bounds__(FTHREADS, 4)
qbn_fused(const float* __restrict__ x,
          const float* __restrict__ weight,
          const float* __restrict__ bias,
          float* __restrict__ out) {
    __shared__ float  sh_s[FTHREADS / 32], sh_q[FTHREADS / 32];
    __shared__ float4 sh_p;

    const int b = blockIdx.x;
    const int t = threadIdx.x;
    const int c = b >> 3;             // channel: 8 bid-contiguous blocks each
    const int n = b & 7;              // batch index -> slice (n,c)

    const size_t base = (size_t)(n * NC + c) * SLICE_F4;
    const float4* xs = reinterpret_cast<const float4*>(x)  + base;
    float4*       ys = reinterpret_cast<float4*>(out)      + base;

    // ---------------- Phase 1: reduce own slice (policy-split) ----------------
    float s = 0.f, sq = 0.f;

    #pragma unroll 1
    for (int g = 0; g < 8; g++) {     // first half: evict-first (dead until phase 2)
        float4 v[4];
        #pragma unroll
        for (int k = 0; k < 4; k++)
            v[k] = __ldcs(xs + (g * 4 + k) * FTHREADS + t);
        #pragma unroll
        for (int k = 0; k < 4; k++) {
            float2 a  = fq2(v[k].x, v[k].y);
            float2 b2 = fq2(v[k].z, v[k].w);
            s  += (a.x + a.y) + (b2.x + b2.y);
            sq += a.x*a.x + a.y*a.y + b2.x*b2.x + b2.y*b2.y;
        }
    }
    #pragma unroll 1
    for (int g = 8; g < 16; g++) {    // second half: default policy -> stays in L2
        float4 v[4];
        #pragma unroll
        for (int k = 0; k < 4; k++)
            v[k] = xs[(g * 4 + k) * FTHREADS + t];
        #pragma unroll
        for (int k = 0; k < 4; k++) {
            float2 a  = fq2(v[k].x, v[k].y);
            float2 b2 = fq2(v[k].z, v[k].w);
            s  += (a.x + a.y) + (b2.x + b2.y);
            sq += a.x*a.x + a.y*a.y + b2.x*b2.x + b2.y*b2.y;
        }
    }

    const int lane = t & 31, w = t >> 5;
    #pragma unroll
    for (int o = 16; o > 0; o >>= 1) {
        s  += __shfl_down_sync(0xffffffffu, s,  o);
        sq += __shfl_down_sync(0xffffffffu, sq, o);
    }
    if (lane == 0) { sh_s[w] = s; sh_q[w] = sq; }
    __syncthreads();
    if (w == 0) {
        s  = (lane < FTHREADS / 32) ? sh_s[lane] : 0.f;
        sq = (lane < FTHREADS / 32) ? sh_q[lane] : 0.f;
        #pragma unroll
        for (int o = 8; o > 0; o >>= 1) {
            s  += __shfl_down_sync(0xffffffffu, s,  o);
            sq += __shfl_down_sync(0xffffffffu, sq, o);
        }
        if (lane == 0) {
            g_psum[c * PARTS + n] = s;
            g_psq [c * PARTS + n] = sq;
            unsigned old;
            asm volatile("atom.release.gpu.global.add.u32 %0, [%1], %2;"
                         : "=r"(old) : "l"(&g_cnt[c]), "r"(1u) : "memory");
            (void)old;
        }
    }

    // ------- Per-channel barrier (8 co-resident blocks) + param finalize -------
    if (t < PARTS) {
        unsigned vv;
        for (;;) {
            asm volatile("ld.acquire.gpu.global.u32 %0, [%1];"
                         : "=r"(vv) : "l"(&g_cnt[c]) : "memory");
            if (vv >= (unsigned)PARTS) break;
            __nanosleep(64);
        }
        float ss = g_psum[c * PARTS + t];
        float qq = g_psq [c * PARTS + t];
        #pragma unroll
        for (int o = 4; o > 0; o >>= 1) {
            ss += __shfl_down_sync(0xffu, ss, o);
            qq += __shfl_down_sync(0xffu, qq, o);
        }
        if (t == 0) {
            // Reset handshake: 8th block past the barrier reclaims the counters.
            unsigned old = atomicAdd(&g_passed[c], 1u);
            if (old == (unsigned)(PARTS - 1)) { g_cnt[c] = 0u; g_passed[c] = 0u; }

            const float inv_n = 1.0f / (float)CPC;
            float mean = ss * inv_n;
            float var  = qq * inv_n - mean * mean;
            float mean_q  = fq1(mean);
            float var_q   = fq1(var);
            float inv_std = 1.0f / sqrtf(var_q + 1e-5f);
            float w_q     = fq1(weight[c]);
            float b_q     = fq1(bias[c]);
            sh_p = make_float4(mean_q, inv_std, w_q, b_q);
        }
    }
    __syncthreads();
    const float4 p = sh_p;            // {mean, inv_std, w, b}

    // ------- Phase 2: backward walk (L2-resident second half first) -------
    #pragma unroll 1
    for (int g = 15; g >= 0; g--) {
        float4 v[4];
        #pragma unroll
        for (int k = 0; k < 4; k++)
            v[k] = __ldcs(xs + (g * 4 + k) * FTHREADS + t);
        #pragma unroll
        for (int k = 0; k < 4; k++) {
            float2 a  = fq2(v[k].x, v[k].y);
            float2 b2 = fq2(v[k].z, v[k].w);
            float y0 = fmaf(p.z, (a.x  - p.x) * p.y, p.w);
            float y1 = fmaf(p.z, (a.y  - p.x) * p.y, p.w);
            float y2 = fmaf(p.z, (b2.x - p.x) * p.y, p.w);
            float y3 = fmaf(p.z, (b2.y - p.x) * p.y, p.w);
            float2 q0 = fq2(y0, y1);
            float2 q1 = fq2(y2, y3);
            __stcs(ys + (g * 4 + k) * FTHREADS + t,
                   make_float4(q0.x, q0.y, q1.x, q1.y));
        }
    }
}

extern "C" void kernel_launch(void* const* d_in, const int* in_sizes, int n_in,
                              void* d_out, int out_size) {
    const float* x      = (const float*)d_in[0];
    const float* weight = (const float*)d_in[1];
    const float* bias   = (const float*)d_in[2];
    float* out = (float*)d_out;

    qbn_fused<<<FBLOCKS, FTHREADS>>>(x, weight, bias, out);
}